// round 15
// baseline (speedup 1.0000x reference)
#include <cuda_runtime.h>
#include <cuda_bf16.h>
#include <math.h>
#include <stdint.h>

#define NW    2048
#define NBINS 1024
#define NH    16
#define HD    64

// ---------------- scratch (device globals: allocation-free) ----------------
__device__ float g_lin[3][NW][NBINS];          // post-projection q/k/v (pre-conv)
__device__ float g_v[NW][NBINS];               // post-conv V fp32
__device__ __nv_bfloat16 g_qb[NW][NBINS];      // post-conv Q, bf16
__device__ __nv_bfloat16 g_kb[NW][NBINS];      // post-conv K, bf16
__device__ __nv_bfloat16 g_rwb[NW][HD];        // relw^T bf16
__device__ __nv_bfloat16 g_vth[NH][HD][NW];    // V^T per head, hi part
__device__ __nv_bfloat16 g_vtl[NH][HD][NW];    // V^T per head, lo part
__device__ float g_l[NH * NW];                 // softmax row sum (atomic acc)
__device__ __nv_bfloat16 g_ph[NH][NW][NW];     // P = exp(qk) hi  (128MB)
__device__ __nv_bfloat16 g_pl[NH][NW][NW];     // P lo            (128MB)
// bf16 pre-converted GEMM operands
__device__ __nv_bfloat16 g_xh[NW][NBINS], g_xl[NW][NBINS];       // x hi/lo
__device__ __nv_bfloat16 g_wqh[NBINS][NBINS], g_wkh[NBINS][NBINS];
__device__ __nv_bfloat16 g_wvh[NBINS][NBINS], g_wvl[NBINS][NBINS];
__device__ __nv_bfloat16 g_woh[NBINS][NBINS], g_wol[NBINS][NBINS];
__device__ __nv_bfloat16 g_oh[NW][NBINS], g_ol[NW][NBINS];       // attn out hi/lo

// ======================= PTX helpers (generic sm_80+) ======================
__device__ __forceinline__ uint32_t smem_u32(const void* p) {
    uint32_t a;
    asm("{ .reg .u64 t; cvta.to.shared.u64 t, %1; cvt.u32.u64 %0, t; }"
        : "=r"(a) : "l"(p));
    return a;
}
__device__ __forceinline__ void ldm_x4(uint32_t r[4], uint32_t addr) {
    asm volatile("ldmatrix.sync.aligned.m8n8.x4.shared.b16 {%0,%1,%2,%3}, [%4];"
                 : "=r"(r[0]), "=r"(r[1]), "=r"(r[2]), "=r"(r[3]) : "r"(addr));
}
__device__ __forceinline__ void ldm_x4_t(uint32_t r[4], uint32_t addr) {
    asm volatile("ldmatrix.sync.aligned.m8n8.x4.trans.shared.b16 {%0,%1,%2,%3}, [%4];"
                 : "=r"(r[0]), "=r"(r[1]), "=r"(r[2]), "=r"(r[3]) : "r"(addr));
}
__device__ __forceinline__ void mma_16816(float c[4], const uint32_t a[4],
                                          uint32_t b0, uint32_t b1) {
    asm volatile(
        "mma.sync.aligned.m16n8k16.row.col.f32.bf16.bf16.f32 "
        "{%0,%1,%2,%3}, {%4,%5,%6,%7}, {%8,%9}, {%0,%1,%2,%3};"
        : "+f"(c[0]), "+f"(c[1]), "+f"(c[2]), "+f"(c[3])
        : "r"(a[0]), "r"(a[1]), "r"(a[2]), "r"(a[3]), "r"(b0), "r"(b1));
}
#define CP16(dst, src) \
    asm volatile("cp.async.cg.shared.global [%0], [%1], 16;" \
                 :: "r"(dst), "l"(src))
#define CP_COMMIT() asm volatile("cp.async.commit_group;")
#define CP_WAIT1()  asm volatile("cp.async.wait_group 1;")
#define CP_WAIT0()  asm volatile("cp.async.wait_group 0;")

// split a float4 into hi/lo bf16 quads and store (8B each)
__device__ __forceinline__ void split_store(float4 v, __nv_bfloat16* ph,
                                            __nv_bfloat16* pl) {
    __nv_bfloat16 hh[4], ll[4];
#pragma unroll
    for (int i = 0; i < 4; i++) {
        float f = (&v.x)[i];
        hh[i] = __float2bfloat16(f);
        ll[i] = __float2bfloat16(f - __bfloat162float(hh[i]));
    }
    *(uint2*)ph = *(uint2*)hh;
    *(uint2*)pl = *(uint2*)ll;
}
__device__ __forceinline__ void hi_store(float4 v, __nv_bfloat16* ph) {
    __nv_bfloat16 hh[4];
#pragma unroll
    for (int i = 0; i < 4; i++) hh[i] = __float2bfloat16((&v.x)[i]);
    *(uint2*)ph = *(uint2*)hh;
}

// ===== pipelined bf16 GEMM body (R13 config): C[m0+64, n0+128], K=1024 ======
// 4 warps / 128 threads; warp tile 32m x 64n; 55KB smem, 4 blocks/SM.
#define GP_A_SZ  (64 * 40)      // [64][40] bf16
#define GP_B_SZ  (32 * 136)     // [32][136] bf16
#define GP_OFF_AL  GP_A_SZ
#define GP_OFF_BH  (2 * GP_A_SZ)
#define GP_OFF_BL  (2 * GP_A_SZ + GP_B_SZ)
#define GP_STAGE   (2 * GP_A_SZ + 2 * GP_B_SZ)      // 13824 bf16
#define GP_SMEM    (2 * GP_STAGE * 2)               // 55296 B

__device__ __forceinline__ void gemm_pipe_body(
    const __nv_bfloat16* __restrict__ Ahp, const __nv_bfloat16* __restrict__ Alp,
    const __nv_bfloat16* __restrict__ Bhp, const __nv_bfloat16* __restrict__ Blp,
    float* __restrict__ C, const bool full, const int m0, const int n0)
{
    extern __shared__ __nv_bfloat16 ps[];
    const int t = threadIdx.x, wid = t >> 5, lane = t & 31;
    const int wm = wid >> 1, wn = wid & 1;  // warp tile 32(m) x 64(n)

    float acc[2][8][4];
#pragma unroll
    for (int mi = 0; mi < 2; mi++)
#pragma unroll
        for (int o = 0; o < 8; o++)
#pragma unroll
            for (int e = 0; e < 4; e++) acc[mi][o][e] = 0.f;

    const uint32_t sbase = smem_u32(ps);

    auto load_stage = [&](int ki, int s) {
        const int kb = ki * 32;
        const uint32_t st = sbase + (uint32_t)(s * GP_STAGE) * 2;
#pragma unroll
        for (int u4 = 0; u4 < 2; u4++) {          // A hi: 256 x 16B
            int u = t + 128 * u4;
            int r = u >> 2, c = u & 3;
            CP16(st + (uint32_t)(r * 40 + c * 8) * 2,
                 Ahp + (size_t)(m0 + r) * 1024 + kb + c * 8);
        }
#pragma unroll
        for (int u4 = 0; u4 < 4; u4++) {          // B hi: 512 x 16B
            int u = t + 128 * u4;
            int r = u >> 4, c = u & 15;
            CP16(st + (uint32_t)(GP_OFF_BH + r * 136 + c * 8) * 2,
                 Bhp + (size_t)(kb + r) * 1024 + n0 + c * 8);
        }
        if (full) {
#pragma unroll
            for (int u4 = 0; u4 < 2; u4++) {      // A lo
                int u = t + 128 * u4;
                int r = u >> 2, c = u & 3;
                CP16(st + (uint32_t)(GP_OFF_AL + r * 40 + c * 8) * 2,
                     Alp + (size_t)(m0 + r) * 1024 + kb + c * 8);
            }
#pragma unroll
            for (int u4 = 0; u4 < 4; u4++) {      // B lo
                int u = t + 128 * u4;
                int r = u >> 4, c = u & 15;
                CP16(st + (uint32_t)(GP_OFF_BL + r * 136 + c * 8) * 2,
                     Blp + (size_t)(kb + r) * 1024 + n0 + c * 8);
            }
        }
    };

    load_stage(0, 0);
    CP_COMMIT();

    const int g = lane >> 3;
    for (int ki = 0; ki < 32; ki++) {
        const int s = ki & 1;
        if (ki < 31) {
            load_stage(ki + 1, s ^ 1);
            CP_COMMIT();
            CP_WAIT1();
        } else {
            CP_WAIT0();
        }
        __syncthreads();

        const uint32_t bAh = sbase + (uint32_t)(s * GP_STAGE) * 2;
        const uint32_t bAl = bAh + (uint32_t)GP_OFF_AL * 2;
        const uint32_t bBh = sbase + (uint32_t)(s * GP_STAGE + GP_OFF_BH) * 2;
        const uint32_t bBl = sbase + (uint32_t)(s * GP_STAGE + GP_OFF_BL) * 2;
#pragma unroll
        for (int kk = 0; kk < 32; kk += 16) {
            uint32_t ah[2][4], al[2][4], bb[8][2];
#pragma unroll
            for (int mi = 0; mi < 2; mi++) {
                uint32_t off = (uint32_t)((wm * 32 + mi * 16 + (lane & 15)) * 40
                                          + kk + (lane >> 4) * 8) * 2;
                ldm_x4(ah[mi], bAh + off);
                if (full) ldm_x4(al[mi], bAl + off);
            }
#pragma unroll
            for (int g4 = 0; g4 < 4; g4++) {      // B hi frags via trans
                uint32_t off = (uint32_t)((kk + (g >> 1) * 8 + (lane & 7)) * 136
                                          + wn * 64 + g4 * 16 + (g & 1) * 8) * 2;
                uint32_t r4[4];
                ldm_x4_t(r4, bBh + off);
                bb[g4 * 2 + 0][0] = r4[0]; bb[g4 * 2 + 0][1] = r4[2];
                bb[g4 * 2 + 1][0] = r4[1]; bb[g4 * 2 + 1][1] = r4[3];
            }
#pragma unroll
            for (int mi = 0; mi < 2; mi++)
#pragma unroll
                for (int o = 0; o < 8; o++)
                    mma_16816(acc[mi][o], ah[mi], bb[o][0], bb[o][1]);
            if (full) {
#pragma unroll
                for (int mi = 0; mi < 2; mi++)
#pragma unroll
                    for (int o = 0; o < 8; o++)
                        mma_16816(acc[mi][o], al[mi], bb[o][0], bb[o][1]);
#pragma unroll
                for (int g4 = 0; g4 < 4; g4++) {  // B lo frags
                    uint32_t off = (uint32_t)((kk + (g >> 1) * 8 + (lane & 7)) * 136
                                              + wn * 64 + g4 * 16 + (g & 1) * 8) * 2;
                    uint32_t r4[4];
                    ldm_x4_t(r4, bBl + off);
                    bb[g4 * 2 + 0][0] = r4[0]; bb[g4 * 2 + 0][1] = r4[2];
                    bb[g4 * 2 + 1][0] = r4[1]; bb[g4 * 2 + 1][1] = r4[3];
                }
#pragma unroll
                for (int mi = 0; mi < 2; mi++)
#pragma unroll
                    for (int o = 0; o < 8; o++)
                        mma_16816(acc[mi][o], ah[mi], bb[o][0], bb[o][1]);
            }
        }
        __syncthreads();
    }

#pragma unroll
    for (int mi = 0; mi < 2; mi++)
#pragma unroll
        for (int o = 0; o < 8; o++)
#pragma unroll
            for (int half = 0; half < 2; half++) {
                int row = m0 + wm * 32 + mi * 16 + (lane >> 2) + half * 8;
                int col = n0 + wn * 64 + o * 8 + (lane & 3) * 2;
                float2 w;
                w.x = acc[mi][o][half * 2 + 0];
                w.y = acc[mi][o][half * 2 + 1];
                *(float2*)&C[(size_t)row * 1024 + col] = w;
            }
}

// K1: all three projections in ONE launch (z picks weight + precision)
__global__ void __launch_bounds__(128, 4)
proj3_kernel()
{
    const int z = blockIdx.z;
    const __nv_bfloat16* Bh;
    const __nv_bfloat16* Bl = nullptr;
    bool full = false;
    if (z == 0)      Bh = &g_wqh[0][0];
    else if (z == 1) Bh = &g_wkh[0][0];
    else { Bh = &g_wvh[0][0]; Bl = &g_wvl[0][0]; full = true; }
    gemm_pipe_body(&g_xh[0][0], full ? &g_xl[0][0] : nullptr, Bh, Bl,
                   &g_lin[z][0][0], full, blockIdx.y * 64, blockIdx.x * 128);
}

// K6: out = g_o @ Wo (full split)
__global__ void __launch_bounds__(128, 4)
out_pipe_kernel(float* __restrict__ out)
{
    gemm_pipe_body(&g_oh[0][0], &g_ol[0][0], &g_woh[0][0], &g_wol[0][0],
                   out, true, blockIdx.y * 64, blockIdx.x * 128);
}

// K0: zero the row-sum accumulator
__global__ void zero_l_kernel()
{
    g_l[blockIdx.x * 256 + threadIdx.x] = 0.f;
}

// K0b: x -> bf16 hi/lo
__global__ void cvt_x_kernel(const float* __restrict__ x)
{
    int i4 = blockIdx.x * 256 + threadIdx.x;     // 2048*1024/4 float4s
    float4 v = ((const float4*)x)[i4];
    split_store(v, &g_xh[0][0] + i4 * 4, &g_xl[0][0] + i4 * 4);
}

// K0c: weights -> bf16 (Wq,Wk hi only; Wv,Wo hi+lo)
__global__ void cvt_w_kernel(const float* __restrict__ Wq, const float* __restrict__ Wk,
                             const float* __restrict__ Wv, const float* __restrict__ Wo)
{
    int z  = blockIdx.y;
    int i4 = blockIdx.x * 256 + threadIdx.x;     // 1024*1024/4
    const float* src = (z == 0) ? Wq : (z == 1) ? Wk : (z == 2) ? Wv : Wo;
    float4 v = ((const float4*)src)[i4];
    if (z == 0)      hi_store(v, &g_wqh[0][0] + i4 * 4);
    else if (z == 1) hi_store(v, &g_wkh[0][0] + i4 * 4);
    else if (z == 2) split_store(v, &g_wvh[0][0] + i4 * 4, &g_wvl[0][0] + i4 * 4);
    else             split_store(v, &g_woh[0][0] + i4 * 4, &g_wol[0][0] + i4 * 4);
}

// K2: depthwise conv; Q,K as bf16, V fp32
__global__ void conv_kernel(const float* __restrict__ cq,
                            const float* __restrict__ ck,
                            const float* __restrict__ cv)
{
    int idx = blockIdx.x * 256 + threadIdx.x;
    int z   = idx / (NW * NBINS);
    int rem = idx - z * (NW * NBINS);
    int w   = rem >> 10;
    int c   = rem & 1023;
    const float* cw = (z == 0) ? cq : (z == 1 ? ck : cv);
    float w0 = cw[c * 3 + 0], w1 = cw[c * 3 + 1], w2 = cw[c * 3 + 2];
    float acc = g_lin[z][w][c] * w1;
    if (w > 0)      acc += g_lin[z][w - 1][c] * w0;
    if (w < NW - 1) acc += g_lin[z][w + 1][c] * w2;
    if (z == 0)      g_qb[w][c] = __float2bfloat16(acc);
    else if (z == 1) g_kb[w][c] = __float2bfloat16(acc);
    else             g_v[w][c]  = acc;
}

// K2b: relw transpose + bf16 convert
__global__ void relw_cvt_kernel(const float* __restrict__ relw)
{
    int idx = blockIdx.x * 256 + threadIdx.x;   // 64*2048
    int d = idx >> 11, i = idx & 2047;
    g_rwb[i][d] = __float2bfloat16(relw[idx]);
}

// K2c: V -> per-head transposed hi/lo bf16 (tiled 64x64 transpose)
__global__ void __launch_bounds__(256)
vt_split_kernel()
{
    __shared__ float tile[64][65];
    const int w0 = blockIdx.x * 64, h = blockIdx.y;
    const int t = threadIdx.x;
#pragma unroll
    for (int s = 0; s < 4; s++) {
        int e = t + 256 * s;
        int r = e >> 4, c4 = e & 15;
        float4 v = *(const float4*)&g_v[w0 + r][h * 64 + c4 * 4];
        tile[r][c4 * 4 + 0] = v.x; tile[r][c4 * 4 + 1] = v.y;
        tile[r][c4 * 4 + 2] = v.z; tile[r][c4 * 4 + 3] = v.w;
    }
    __syncthreads();
#pragma unroll
    for (int s = 0; s < 4; s++) {
        int e = t + 256 * s;
        int d = e >> 4, w4 = e & 15;
        __nv_bfloat16 hh[4], ll[4];
#pragma unroll
        for (int i = 0; i < 4; i++) {
            float f = tile[w4 * 4 + i][d];
            hh[i] = __float2bfloat16(f);
            ll[i] = __float2bfloat16(f - __bfloat162float(hh[i]));
        }
        *(uint2*)&g_vth[h][d][w0 + w4 * 4] = *(uint2*)hh;
        *(uint2*)&g_vtl[h][d][w0 + w4 * 4] = *(uint2*)ll;
    }
}

// K3: qk via mma.sync bf16; staged coalesced epilogue computes qk, row sums,
// AND P = exp(qk) split to bf16 hi/lo (so av never recomputes exp).
#define QK_RS 72
__global__ void __launch_bounds__(256)
qk_mma_kernel(const float* __restrict__ prev, float* __restrict__ qk)
{
    extern __shared__ __nv_bfloat16 smb[];
    __nv_bfloat16* sQi = smb;
    __nv_bfloat16* sKj = smb + 128 * QK_RS;
    __nv_bfloat16* sQj = smb + 2 * 128 * QK_RS;
    __nv_bfloat16* sRw = smb + 3 * 128 * QK_RS;

    const int t = threadIdx.x, wid = t >> 5, lane = t & 31;
    const int j0 = blockIdx.x * 128, i0 = blockIdx.y * 128, h = blockIdx.z;

    {
        const int r = t & 127;
        const int ch0 = (t >> 7) * 4;
        const uint4* qi = (const uint4*)&g_qb[i0 + r][h * 64];
        const uint4* kj = (const uint4*)&g_kb[j0 + r][h * 64];
        const uint4* qj = (const uint4*)&g_qb[j0 + r][h * 64];
        const uint4* rw = (const uint4*)&g_rwb[i0 + r][0];
#pragma unroll
        for (int c = 0; c < 4; c++) {
            int c16 = ch0 + c;
            *(uint4*)((char*)sQi + r * 144 + c16 * 16) = qi[c16];
            *(uint4*)((char*)sKj + r * 144 + c16 * 16) = kj[c16];
            *(uint4*)((char*)sQj + r * 144 + c16 * 16) = qj[c16];
            *(uint4*)((char*)sRw + r * 144 + c16 * 16) = rw[c16];
        }
    }
    __syncthreads();

    const int wm = wid & 1;
    const int wn = wid >> 1;
    const uint32_t sbQi = smem_u32(sQi), sbKj = smem_u32(sKj);
    const uint32_t sbQj = smem_u32(sQj), sbRw = smem_u32(sRw);

    float c[4][4][4];
#pragma unroll
    for (int mi = 0; mi < 4; mi++)
#pragma unroll
        for (int ni = 0; ni < 4; ni++)
#pragma unroll
            for (int e = 0; e < 4; e++) c[mi][ni][e] = 0.f;

#pragma unroll
    for (int term = 0; term < 2; term++) {
        const uint32_t sbA = term ? sbRw : sbQi;
        const uint32_t sbB = term ? sbQj : sbKj;
#pragma unroll
        for (int ks = 0; ks < 4; ks++) {
            const int kcol = ks * 16 + (lane >> 4) * 8;
            uint32_t a[4][4];
#pragma unroll
            for (int mi = 0; mi < 4; mi++) {
                int row = wm * 64 + mi * 16 + (lane & 15);
                ldm_x4(a[mi], sbA + (uint32_t)(row * 144 + kcol * 2));
            }
            uint32_t b[4][2];
#pragma unroll
            for (int nh = 0; nh < 2; nh++) {
                int row = wn * 32 + nh * 16 + (lane & 15);
                uint32_t r4[4];
                ldm_x4(r4, sbB + (uint32_t)(row * 144 + kcol * 2));
                b[nh * 2 + 0][0] = r4[0]; b[nh * 2 + 0][1] = r4[2];
                b[nh * 2 + 1][0] = r4[1]; b[nh * 2 + 1][1] = r4[3];
            }
#pragma unroll
            for (int mi = 0; mi < 4; mi++)
#pragma unroll
                for (int ni = 0; ni < 4; ni++)
                    mma_16816(c[mi][ni], a[mi], b[ni][0], b[ni][1]);
        }
    }

    // ---- staged epilogue: accumulators -> smem (fragment layout) ----
    __syncthreads();
    float* sC = (float*)smb;               // [128][132]
    const float inv = 1.0f / 32.0f;
    const int qr = lane >> 2, qc = (lane & 3) * 2;
#pragma unroll
    for (int mi = 0; mi < 4; mi++)
#pragma unroll
        for (int ni = 0; ni < 4; ni++)
#pragma unroll
            for (int half = 0; half < 2; half++) {
                int row = wm * 64 + mi * 16 + qr + half * 8;
                int col = wn * 32 + ni * 8 + qc;
                float2 w;
                w.x = c[mi][ni][half * 2 + 0] * inv;
                w.y = c[mi][ni][half * 2 + 1] * inv;
                *(float2*)&sC[row * 132 + col] = w;
            }
    __syncthreads();

    // coalesced: prev + qk write + P hi/lo write + row sums
    const size_t base = ((size_t)(h * 2048 + i0)) * 2048 + j0;
#pragma unroll
    for (int s = 0; s < 16; s++) {
        int r = 8 * s + wid;
        size_t off = base + (size_t)r * 2048 + lane * 4;
        float4 p = *(const float4*)&prev[off];
        float4 v = *(const float4*)&sC[r * 132 + lane * 4];
        float4 o;
        o.x = v.x + p.x; o.y = v.y + p.y; o.z = v.z + p.z; o.w = v.w + p.w;
        *(float4*)&qk[off] = o;
        float4 pe;
        pe.x = __expf(o.x); pe.y = __expf(o.y);
        pe.z = __expf(o.z); pe.w = __expf(o.w);
        split_store(pe, &g_ph[h][i0 + r][j0 + lane * 4],
                        &g_pl[h][i0 + r][j0 + lane * 4]);
        float es = pe.x + pe.y + pe.z + pe.w;
#pragma unroll
        for (int d = 16; d > 0; d >>= 1)
            es += __shfl_xor_sync(0xffffffffu, es, d);
        if (lane == 0) atomicAdd(&g_l[h * 2048 + i0 + r], es);
    }
}

// K5: AV via split-bf16 mma; P hi/lo loaded directly (no exp, no split).
#define AV_SMEM 104448
__global__ void __launch_bounds__(256, 2)
av_mma_kernel()
{
    extern __shared__ __nv_bfloat16 avs[];
    __nv_bfloat16* sPh = avs;                       // [128][136]
    __nv_bfloat16* sPl = avs + 128 * 136;
    __nv_bfloat16* sVh = avs + 2 * 128 * 136;       // [64][136]
    __nv_bfloat16* sVl = avs + 2 * 128 * 136 + 64 * 136;
    const int i0 = blockIdx.x * 128, h = blockIdx.y;
    const int t = threadIdx.x, wid = t >> 5, lane = t & 31;
    const int wm = wid >> 1, wn = wid & 1;          // warp tile 32(m) x 32(n)

    float acc[2][4][4];
#pragma unroll
    for (int mi = 0; mi < 2; mi++)
#pragma unroll
        for (int o = 0; o < 4; o++)
#pragma unroll
            for (int e = 0; e < 4; e++) acc[mi][o][e] = 0.f;

    for (int jb = 0; jb < 16; jb++) {
        const int j0 = jb * 128;
#pragma unroll
        for (int s = 0; s < 8; s++) {               // P hi/lo: 128x16 chunks
            int e = t + 256 * s;
            int r = e >> 4, c16 = e & 15;
            *(uint4*)&sPh[r * 136 + c16 * 8] =
                *(const uint4*)&g_ph[h][i0 + r][j0 + c16 * 8];
            *(uint4*)&sPl[r * 136 + c16 * 8] =
                *(const uint4*)&g_pl[h][i0 + r][j0 + c16 * 8];
        }
#pragma unroll
        for (int s = 0; s < 8; s++) {               // V^T tiles hi/lo
            int e = t + 256 * s;
            int d = e >> 5, c4 = e & 31;
            *(uint2*)&sVh[d * 136 + c4 * 4] = *(const uint2*)&g_vth[h][d][j0 + c4 * 4];
            *(uint2*)&sVl[d * 136 + c4 * 4] = *(const uint2*)&g_vtl[h][d][j0 + c4 * 4];
        }
        __syncthreads();
        const uint32_t bPh = smem_u32(sPh), bPl = smem_u32(sPl);
        const uint32_t bVh = smem_u32(sVh), bVl = smem_u32(sVl);
#pragma unroll
        for (int kk = 0; kk < 128; kk += 16) {
            uint32_t ah[2][4], al[2][4], bv[4][2];
#pragma unroll
            for (int mi = 0; mi < 2; mi++) {
                uint32_t off = (uint32_t)((wm * 32 + mi * 16 + (lane & 15)) * 136
                                          + kk + (lane >> 4) * 8) * 2;
                ldm_x4(ah[mi], bPh + off);
                ldm_x4(al[mi], bPl + off);
            }
#pragma unroll
            for (int nb = 0; nb < 2; nb++) {        // Vh frags
                uint32_t off = (uint32_t)((wn * 32 + nb * 16 + (lane & 15)) * 136
                                          + kk + (lane >> 4) * 8) * 2;
                uint32_t r4[4];
                ldm_x4(r4, bVh + off);
                bv[nb * 2 + 0][0] = r4[0]; bv[nb * 2 + 0][1] = r4[2];
                bv[nb * 2 + 1][0] = r4[1]; bv[nb * 2 + 1][1] = r4[3];
            }
#pragma unroll
            for (int mi = 0; mi < 2; mi++)
#pragma unroll
                for (int o = 0; o < 4; o++) {
                    mma_16816(acc[mi][o], ah[mi], bv[o][0], bv[o][1]);
                    mma_16816(acc[mi][o], al[mi], bv[o][0], bv[o][1]);
                }
#pragma unroll
            for (int nb = 0; nb < 2; nb++) {        // Vl frags
                uint32_t off = (uint32_t)((wn * 32 + nb * 16 + (lane & 15)) * 136
                                          + kk + (lane >> 4) * 8) * 2;
                uint32_t r4[4];
                ldm_x4(r4, bVl + off);
                bv[nb * 2 + 0][0] = r4[0]; bv[nb * 2 + 0][1] = r4[2];
                bv[nb * 2 + 1][0] = r4[1]; bv[nb * 2 + 1][1] = r4[3];
            }
#pragma unroll
            for (int mi = 0; mi < 2; mi++)
#pragma unroll
                for (int o = 0; o < 4; o++)
                    mma_16816(acc[mi][o], ah[mi], bv[o][0], bv[o][1]);
        }
        __syncthreads();
    }
#pragma unroll
    for (int mi = 0; mi < 2; mi++)
#pragma unroll
        for (int o = 0; o < 4; o++)
#pragma unroll
            for (int half = 0; half < 2; half++) {
                int row = i0 + wm * 32 + mi * 16 + (lane >> 2) + half * 8;
                float invl = 1.0f / g_l[h * 2048 + row];
                int col = h * 64 + wn * 32 + o * 8 + (lane & 3) * 2;
                float o0 = acc[mi][o][half * 2 + 0] * invl;
                float o1 = acc[mi][o][half * 2 + 1] * invl;
                __nv_bfloat16 h0 = __float2bfloat16(o0);
                __nv_bfloat16 h1 = __float2bfloat16(o1);
                __nv_bfloat16 l0 = __float2bfloat16(o0 - __bfloat162float(h0));
                __nv_bfloat16 l1 = __float2bfloat16(o1 - __bfloat162float(h1));
                __nv_bfloat162 ph; ph.x = h0; ph.y = h1;
                __nv_bfloat162 pl; pl.x = l0; pl.y = l1;
                *(__nv_bfloat162*)&g_oh[row][col] = ph;
                *(__nv_bfloat162*)&g_ol[row][col] = pl;
            }
}

// --------------------------------------------------------------------------
extern "C" void kernel_launch(void* const* d_in, const int* in_sizes, int n_in,
                              void* d_out, int out_size)
{
    const float* x    = (const float*)d_in[0];
    const float* prev = (const float*)d_in[1];
    const float* Wq   = (const float*)d_in[2];
    const float* Wk   = (const float*)d_in[3];
    const float* Wv   = (const float*)d_in[4];
    const float* Wo   = (const float*)d_in[5];
    const float* cq   = (const float*)d_in[6];
    const float* ck   = (const float*)d_in[7];
    const float* cv   = (const float*)d_in[8];
    const float* relw = (const float*)d_in[9];

    float* out = (float*)d_out;                 // (1,2048,1024)
    float* qk  = out + (size_t)NW * NBINS;      // (1,16,2048,2048)

    const size_t QK_SMEM = (size_t)4 * 128 * QK_RS * sizeof(__nv_bfloat16); // 73728
    cudaFuncSetAttribute(proj3_kernel,    cudaFuncAttributeMaxDynamicSharedMemorySize, GP_SMEM);
    cudaFuncSetAttribute(out_pipe_kernel, cudaFuncAttributeMaxDynamicSharedMemorySize, GP_SMEM);
    cudaFuncSetAttribute(qk_mma_kernel,   cudaFuncAttributeMaxDynamicSharedMemorySize, (int)QK_SMEM);
    cudaFuncSetAttribute(av_mma_kernel,   cudaFuncAttributeMaxDynamicSharedMemorySize, AV_SMEM);

    zero_l_kernel<<<(NH * NW) / 256, 256>>>();
    cvt_x_kernel<<<(NW * NBINS) / 1024, 256>>>(x);
    cvt_w_kernel<<<dim3((NBINS * NBINS) / 1024, 4), 256>>>(Wq, Wk, Wv, Wo);

    proj3_kernel<<<dim3(8, 32, 3), 128, GP_SMEM>>>();

    conv_kernel<<<(3 * NW * NBINS) / 256, 256>>>(cq, ck, cv);
    relw_cvt_kernel<<<(HD * NW) / 256, 256>>>(relw);
    vt_split_kernel<<<dim3(32, 16), 256>>>();
    qk_mma_kernel<<<dim3(16, 16, 16), 256, QK_SMEM>>>(prev, qk);
    av_mma_kernel<<<dim3(16, 16), 256, AV_SMEM>>>();
    out_pipe_kernel<<<dim3(8, 32), 128, GP_SMEM>>>(out);
}

// round 16
// speedup vs baseline: 1.0302x; 1.0302x over previous
#include <cuda_runtime.h>
#include <cuda_bf16.h>
#include <math.h>
#include <stdint.h>

#define NW    2048
#define NBINS 1024
#define NH    16
#define HD    64

// ---------------- scratch (device globals: allocation-free) ----------------
__device__ float g_lin[3][NW][NBINS];          // post-projection q/k/v (pre-conv)
__device__ float g_v[NW][NBINS];               // post-conv V fp32
__device__ __nv_bfloat16 g_qb[NW][NBINS];      // post-conv Q, bf16
__device__ __nv_bfloat16 g_kb[NW][NBINS];      // post-conv K, bf16
__device__ __nv_bfloat16 g_rwb[NW][HD];        // relw^T bf16
__device__ __nv_bfloat16 g_vth[NH][HD][NW];    // V^T per head, hi part
__device__ __nv_bfloat16 g_vtl[NH][HD][NW];    // V^T per head, lo part
__device__ float g_l[NH * NW];                 // softmax row sum (atomic acc)
// bf16 pre-converted GEMM operands
__device__ __nv_bfloat16 g_xh[NW][NBINS], g_xl[NW][NBINS];       // x hi/lo
__device__ __nv_bfloat16 g_wqh[NBINS][NBINS], g_wkh[NBINS][NBINS];
__device__ __nv_bfloat16 g_wvh[NBINS][NBINS], g_wvl[NBINS][NBINS];
__device__ __nv_bfloat16 g_woh[NBINS][NBINS], g_wol[NBINS][NBINS];
__device__ __nv_bfloat16 g_oh[NW][NBINS], g_ol[NW][NBINS];       // attn out hi/lo

// ======================= PTX helpers (generic sm_80+) ======================
__device__ __forceinline__ uint32_t smem_u32(const void* p) {
    uint32_t a;
    asm("{ .reg .u64 t; cvta.to.shared.u64 t, %1; cvt.u32.u64 %0, t; }"
        : "=r"(a) : "l"(p));
    return a;
}
__device__ __forceinline__ void ldm_x4(uint32_t r[4], uint32_t addr) {
    asm volatile("ldmatrix.sync.aligned.m8n8.x4.shared.b16 {%0,%1,%2,%3}, [%4];"
                 : "=r"(r[0]), "=r"(r[1]), "=r"(r[2]), "=r"(r[3]) : "r"(addr));
}
__device__ __forceinline__ void ldm_x4_t(uint32_t r[4], uint32_t addr) {
    asm volatile("ldmatrix.sync.aligned.m8n8.x4.trans.shared.b16 {%0,%1,%2,%3}, [%4];"
                 : "=r"(r[0]), "=r"(r[1]), "=r"(r[2]), "=r"(r[3]) : "r"(addr));
}
__device__ __forceinline__ void mma_16816(float c[4], const uint32_t a[4],
                                          uint32_t b0, uint32_t b1) {
    asm volatile(
        "mma.sync.aligned.m16n8k16.row.col.f32.bf16.bf16.f32 "
        "{%0,%1,%2,%3}, {%4,%5,%6,%7}, {%8,%9}, {%0,%1,%2,%3};"
        : "+f"(c[0]), "+f"(c[1]), "+f"(c[2]), "+f"(c[3])
        : "r"(a[0]), "r"(a[1]), "r"(a[2]), "r"(a[3]), "r"(b0), "r"(b1));
}
#define CP16(dst, src) \
    asm volatile("cp.async.cg.shared.global [%0], [%1], 16;" \
                 :: "r"(dst), "l"(src))
#define CP_COMMIT() asm volatile("cp.async.commit_group;")
#define CP_WAIT1()  asm volatile("cp.async.wait_group 1;")
#define CP_WAIT0()  asm volatile("cp.async.wait_group 0;")

// split a float4 into hi/lo bf16 quads and store (8B each)
__device__ __forceinline__ void split_store(float4 v, __nv_bfloat16* ph,
                                            __nv_bfloat16* pl) {
    __nv_bfloat16 hh[4], ll[4];
#pragma unroll
    for (int i = 0; i < 4; i++) {
        float f = (&v.x)[i];
        hh[i] = __float2bfloat16(f);
        ll[i] = __float2bfloat16(f - __bfloat162float(hh[i]));
    }
    *(uint2*)ph = *(uint2*)hh;
    *(uint2*)pl = *(uint2*)ll;
}
__device__ __forceinline__ void hi_store(float4 v, __nv_bfloat16* ph) {
    __nv_bfloat16 hh[4];
#pragma unroll
    for (int i = 0; i < 4; i++) hh[i] = __float2bfloat16((&v.x)[i]);
    *(uint2*)ph = *(uint2*)hh;
}

// ===== pipelined bf16 GEMM body (R13 config): C[m0+64, n0+128], K=1024 ======
// 4 warps / 128 threads; warp tile 32m x 64n; 55KB smem, 4 blocks/SM.
#define GP_A_SZ  (64 * 40)      // [64][40] bf16
#define GP_B_SZ  (32 * 136)     // [32][136] bf16
#define GP_OFF_AL  GP_A_SZ
#define GP_OFF_BH  (2 * GP_A_SZ)
#define GP_OFF_BL  (2 * GP_A_SZ + GP_B_SZ)
#define GP_STAGE   (2 * GP_A_SZ + 2 * GP_B_SZ)      // 13824 bf16
#define GP_SMEM    (2 * GP_STAGE * 2)               // 55296 B

__device__ __forceinline__ void gemm_pipe_body(
    const __nv_bfloat16* __restrict__ Ahp, const __nv_bfloat16* __restrict__ Alp,
    const __nv_bfloat16* __restrict__ Bhp, const __nv_bfloat16* __restrict__ Blp,
    float* __restrict__ C, const bool full, const int m0, const int n0)
{
    extern __shared__ __nv_bfloat16 ps[];
    const int t = threadIdx.x, wid = t >> 5, lane = t & 31;
    const int wm = wid >> 1, wn = wid & 1;  // warp tile 32(m) x 64(n)

    float acc[2][8][4];
#pragma unroll
    for (int mi = 0; mi < 2; mi++)
#pragma unroll
        for (int o = 0; o < 8; o++)
#pragma unroll
            for (int e = 0; e < 4; e++) acc[mi][o][e] = 0.f;

    const uint32_t sbase = smem_u32(ps);

    auto load_stage = [&](int ki, int s) {
        const int kb = ki * 32;
        const uint32_t st = sbase + (uint32_t)(s * GP_STAGE) * 2;
#pragma unroll
        for (int u4 = 0; u4 < 2; u4++) {          // A hi: 256 x 16B
            int u = t + 128 * u4;
            int r = u >> 2, c = u & 3;
            CP16(st + (uint32_t)(r * 40 + c * 8) * 2,
                 Ahp + (size_t)(m0 + r) * 1024 + kb + c * 8);
        }
#pragma unroll
        for (int u4 = 0; u4 < 4; u4++) {          // B hi: 512 x 16B
            int u = t + 128 * u4;
            int r = u >> 4, c = u & 15;
            CP16(st + (uint32_t)(GP_OFF_BH + r * 136 + c * 8) * 2,
                 Bhp + (size_t)(kb + r) * 1024 + n0 + c * 8);
        }
        if (full) {
#pragma unroll
            for (int u4 = 0; u4 < 2; u4++) {      // A lo
                int u = t + 128 * u4;
                int r = u >> 2, c = u & 3;
                CP16(st + (uint32_t)(GP_OFF_AL + r * 40 + c * 8) * 2,
                     Alp + (size_t)(m0 + r) * 1024 + kb + c * 8);
            }
#pragma unroll
            for (int u4 = 0; u4 < 4; u4++) {      // B lo
                int u = t + 128 * u4;
                int r = u >> 4, c = u & 15;
                CP16(st + (uint32_t)(GP_OFF_BL + r * 136 + c * 8) * 2,
                     Blp + (size_t)(kb + r) * 1024 + n0 + c * 8);
            }
        }
    };

    load_stage(0, 0);
    CP_COMMIT();

    const int g = lane >> 3;
    for (int ki = 0; ki < 32; ki++) {
        const int s = ki & 1;
        if (ki < 31) {
            load_stage(ki + 1, s ^ 1);
            CP_COMMIT();
            CP_WAIT1();
        } else {
            CP_WAIT0();
        }
        __syncthreads();

        const uint32_t bAh = sbase + (uint32_t)(s * GP_STAGE) * 2;
        const uint32_t bAl = bAh + (uint32_t)GP_OFF_AL * 2;
        const uint32_t bBh = sbase + (uint32_t)(s * GP_STAGE + GP_OFF_BH) * 2;
        const uint32_t bBl = sbase + (uint32_t)(s * GP_STAGE + GP_OFF_BL) * 2;
#pragma unroll
        for (int kk = 0; kk < 32; kk += 16) {
            uint32_t ah[2][4], al[2][4], bb[8][2];
#pragma unroll
            for (int mi = 0; mi < 2; mi++) {
                uint32_t off = (uint32_t)((wm * 32 + mi * 16 + (lane & 15)) * 40
                                          + kk + (lane >> 4) * 8) * 2;
                ldm_x4(ah[mi], bAh + off);
                if (full) ldm_x4(al[mi], bAl + off);
            }
#pragma unroll
            for (int g4 = 0; g4 < 4; g4++) {      // B hi frags via trans
                uint32_t off = (uint32_t)((kk + (g >> 1) * 8 + (lane & 7)) * 136
                                          + wn * 64 + g4 * 16 + (g & 1) * 8) * 2;
                uint32_t r4[4];
                ldm_x4_t(r4, bBh + off);
                bb[g4 * 2 + 0][0] = r4[0]; bb[g4 * 2 + 0][1] = r4[2];
                bb[g4 * 2 + 1][0] = r4[1]; bb[g4 * 2 + 1][1] = r4[3];
            }
#pragma unroll
            for (int mi = 0; mi < 2; mi++)
#pragma unroll
                for (int o = 0; o < 8; o++)
                    mma_16816(acc[mi][o], ah[mi], bb[o][0], bb[o][1]);
            if (full) {
#pragma unroll
                for (int mi = 0; mi < 2; mi++)
#pragma unroll
                    for (int o = 0; o < 8; o++)
                        mma_16816(acc[mi][o], al[mi], bb[o][0], bb[o][1]);
#pragma unroll
                for (int g4 = 0; g4 < 4; g4++) {  // B lo frags
                    uint32_t off = (uint32_t)((kk + (g >> 1) * 8 + (lane & 7)) * 136
                                              + wn * 64 + g4 * 16 + (g & 1) * 8) * 2;
                    uint32_t r4[4];
                    ldm_x4_t(r4, bBl + off);
                    bb[g4 * 2 + 0][0] = r4[0]; bb[g4 * 2 + 0][1] = r4[2];
                    bb[g4 * 2 + 1][0] = r4[1]; bb[g4 * 2 + 1][1] = r4[3];
                }
#pragma unroll
                for (int mi = 0; mi < 2; mi++)
#pragma unroll
                    for (int o = 0; o < 8; o++)
                        mma_16816(acc[mi][o], ah[mi], bb[o][0], bb[o][1]);
            }
        }
        __syncthreads();
    }

#pragma unroll
    for (int mi = 0; mi < 2; mi++)
#pragma unroll
        for (int o = 0; o < 8; o++)
#pragma unroll
            for (int half = 0; half < 2; half++) {
                int row = m0 + wm * 32 + mi * 16 + (lane >> 2) + half * 8;
                int col = n0 + wn * 64 + o * 8 + (lane & 3) * 2;
                float2 w;
                w.x = acc[mi][o][half * 2 + 0];
                w.y = acc[mi][o][half * 2 + 1];
                *(float2*)&C[(size_t)row * 1024 + col] = w;
            }
}

// K1: all three projections in ONE launch (z picks weight + precision)
__global__ void __launch_bounds__(128, 4)
proj3_kernel()
{
    const int z = blockIdx.z;
    const __nv_bfloat16* Bh;
    const __nv_bfloat16* Bl = nullptr;
    bool full = false;
    if (z == 0)      Bh = &g_wqh[0][0];
    else if (z == 1) Bh = &g_wkh[0][0];
    else { Bh = &g_wvh[0][0]; Bl = &g_wvl[0][0]; full = true; }
    gemm_pipe_body(&g_xh[0][0], full ? &g_xl[0][0] : nullptr, Bh, Bl,
                   &g_lin[z][0][0], full, blockIdx.y * 64, blockIdx.x * 128);
}

// K6: out = g_o @ Wo (full split)
__global__ void __launch_bounds__(128, 4)
out_pipe_kernel(float* __restrict__ out)
{
    gemm_pipe_body(&g_oh[0][0], &g_ol[0][0], &g_woh[0][0], &g_wol[0][0],
                   out, true, blockIdx.y * 64, blockIdx.x * 128);
}

// K0: zero the row-sum accumulator
__global__ void zero_l_kernel()
{
    g_l[blockIdx.x * 256 + threadIdx.x] = 0.f;
}

// K0b: x -> bf16 hi/lo
__global__ void cvt_x_kernel(const float* __restrict__ x)
{
    int i4 = blockIdx.x * 256 + threadIdx.x;     // 2048*1024/4 float4s
    float4 v = ((const float4*)x)[i4];
    split_store(v, &g_xh[0][0] + i4 * 4, &g_xl[0][0] + i4 * 4);
}

// K0c: weights -> bf16 (Wq,Wk hi only; Wv,Wo hi+lo)
__global__ void cvt_w_kernel(const float* __restrict__ Wq, const float* __restrict__ Wk,
                             const float* __restrict__ Wv, const float* __restrict__ Wo)
{
    int z  = blockIdx.y;
    int i4 = blockIdx.x * 256 + threadIdx.x;     // 1024*1024/4
    const float* src = (z == 0) ? Wq : (z == 1) ? Wk : (z == 2) ? Wv : Wo;
    float4 v = ((const float4*)src)[i4];
    if (z == 0)      hi_store(v, &g_wqh[0][0] + i4 * 4);
    else if (z == 1) hi_store(v, &g_wkh[0][0] + i4 * 4);
    else if (z == 2) split_store(v, &g_wvh[0][0] + i4 * 4, &g_wvl[0][0] + i4 * 4);
    else             split_store(v, &g_woh[0][0] + i4 * 4, &g_wol[0][0] + i4 * 4);
}

// K2: depthwise conv; Q,K as bf16, V fp32
__global__ void conv_kernel(const float* __restrict__ cq,
                            const float* __restrict__ ck,
                            const float* __restrict__ cv)
{
    int idx = blockIdx.x * 256 + threadIdx.x;
    int z   = idx / (NW * NBINS);
    int rem = idx - z * (NW * NBINS);
    int w   = rem >> 10;
    int c   = rem & 1023;
    const float* cw = (z == 0) ? cq : (z == 1 ? ck : cv);
    float w0 = cw[c * 3 + 0], w1 = cw[c * 3 + 1], w2 = cw[c * 3 + 2];
    float acc = g_lin[z][w][c] * w1;
    if (w > 0)      acc += g_lin[z][w - 1][c] * w0;
    if (w < NW - 1) acc += g_lin[z][w + 1][c] * w2;
    if (z == 0)      g_qb[w][c] = __float2bfloat16(acc);
    else if (z == 1) g_kb[w][c] = __float2bfloat16(acc);
    else             g_v[w][c]  = acc;
}

// K2b: relw transpose + bf16 convert
__global__ void relw_cvt_kernel(const float* __restrict__ relw)
{
    int idx = blockIdx.x * 256 + threadIdx.x;   // 64*2048
    int d = idx >> 11, i = idx & 2047;
    g_rwb[i][d] = __float2bfloat16(relw[idx]);
}

// K2c: V -> per-head transposed hi/lo bf16 (tiled 64x64 transpose)
__global__ void __launch_bounds__(256)
vt_split_kernel()
{
    __shared__ float tile[64][65];
    const int w0 = blockIdx.x * 64, h = blockIdx.y;
    const int t = threadIdx.x;
#pragma unroll
    for (int s = 0; s < 4; s++) {
        int e = t + 256 * s;
        int r = e >> 4, c4 = e & 15;
        float4 v = *(const float4*)&g_v[w0 + r][h * 64 + c4 * 4];
        tile[r][c4 * 4 + 0] = v.x; tile[r][c4 * 4 + 1] = v.y;
        tile[r][c4 * 4 + 2] = v.z; tile[r][c4 * 4 + 3] = v.w;
    }
    __syncthreads();
#pragma unroll
    for (int s = 0; s < 4; s++) {
        int e = t + 256 * s;
        int d = e >> 4, w4 = e & 15;
        __nv_bfloat16 hh[4], ll[4];
#pragma unroll
        for (int i = 0; i < 4; i++) {
            float f = tile[w4 * 4 + i][d];
            hh[i] = __float2bfloat16(f);
            ll[i] = __float2bfloat16(f - __bfloat162float(hh[i]));
        }
        *(uint2*)&g_vth[h][d][w0 + w4 * 4] = *(uint2*)hh;
        *(uint2*)&g_vtl[h][d][w0 + w4 * 4] = *(uint2*)ll;
    }
}

// K3: qk via mma.sync bf16; staged coalesced epilogue with fused row sums.
#define QK_RS 72
__global__ void __launch_bounds__(256)
qk_mma_kernel(const float* __restrict__ prev, float* __restrict__ qk)
{
    extern __shared__ __nv_bfloat16 smb[];
    __nv_bfloat16* sQi = smb;
    __nv_bfloat16* sKj = smb + 128 * QK_RS;
    __nv_bfloat16* sQj = smb + 2 * 128 * QK_RS;
    __nv_bfloat16* sRw = smb + 3 * 128 * QK_RS;

    const int t = threadIdx.x, wid = t >> 5, lane = t & 31;
    const int j0 = blockIdx.x * 128, i0 = blockIdx.y * 128, h = blockIdx.z;

    {
        const int r = t & 127;
        const int ch0 = (t >> 7) * 4;
        const uint4* qi = (const uint4*)&g_qb[i0 + r][h * 64];
        const uint4* kj = (const uint4*)&g_kb[j0 + r][h * 64];
        const uint4* qj = (const uint4*)&g_qb[j0 + r][h * 64];
        const uint4* rw = (const uint4*)&g_rwb[i0 + r][0];
#pragma unroll
        for (int c = 0; c < 4; c++) {
            int c16 = ch0 + c;
            *(uint4*)((char*)sQi + r * 144 + c16 * 16) = qi[c16];
            *(uint4*)((char*)sKj + r * 144 + c16 * 16) = kj[c16];
            *(uint4*)((char*)sQj + r * 144 + c16 * 16) = qj[c16];
            *(uint4*)((char*)sRw + r * 144 + c16 * 16) = rw[c16];
        }
    }
    __syncthreads();

    const int wm = wid & 1;
    const int wn = wid >> 1;
    const uint32_t sbQi = smem_u32(sQi), sbKj = smem_u32(sKj);
    const uint32_t sbQj = smem_u32(sQj), sbRw = smem_u32(sRw);

    float c[4][4][4];
#pragma unroll
    for (int mi = 0; mi < 4; mi++)
#pragma unroll
        for (int ni = 0; ni < 4; ni++)
#pragma unroll
            for (int e = 0; e < 4; e++) c[mi][ni][e] = 0.f;

#pragma unroll
    for (int term = 0; term < 2; term++) {
        const uint32_t sbA = term ? sbRw : sbQi;
        const uint32_t sbB = term ? sbQj : sbKj;
#pragma unroll
        for (int ks = 0; ks < 4; ks++) {
            const int kcol = ks * 16 + (lane >> 4) * 8;
            uint32_t a[4][4];
#pragma unroll
            for (int mi = 0; mi < 4; mi++) {
                int row = wm * 64 + mi * 16 + (lane & 15);
                ldm_x4(a[mi], sbA + (uint32_t)(row * 144 + kcol * 2));
            }
            uint32_t b[4][2];
#pragma unroll
            for (int nh = 0; nh < 2; nh++) {
                int row = wn * 32 + nh * 16 + (lane & 15);
                uint32_t r4[4];
                ldm_x4(r4, sbB + (uint32_t)(row * 144 + kcol * 2));
                b[nh * 2 + 0][0] = r4[0]; b[nh * 2 + 0][1] = r4[2];
                b[nh * 2 + 1][0] = r4[1]; b[nh * 2 + 1][1] = r4[3];
            }
#pragma unroll
            for (int mi = 0; mi < 4; mi++)
#pragma unroll
                for (int ni = 0; ni < 4; ni++)
                    mma_16816(c[mi][ni], a[mi], b[ni][0], b[ni][1]);
        }
    }

    // ---- staged epilogue: accumulators -> smem (fragment layout) ----
    __syncthreads();
    float* sC = (float*)smb;               // [128][132]
    const float inv = 1.0f / 32.0f;
    const int qr = lane >> 2, qc = (lane & 3) * 2;
#pragma unroll
    for (int mi = 0; mi < 4; mi++)
#pragma unroll
        for (int ni = 0; ni < 4; ni++)
#pragma unroll
            for (int half = 0; half < 2; half++) {
                int row = wm * 64 + mi * 16 + qr + half * 8;
                int col = wn * 32 + ni * 8 + qc;
                float2 w;
                w.x = c[mi][ni][half * 2 + 0] * inv;
                w.y = c[mi][ni][half * 2 + 1] * inv;
                *(float2*)&sC[row * 132 + col] = w;
            }
    __syncthreads();

    const size_t base = ((size_t)(h * 2048 + i0)) * 2048 + j0;
#pragma unroll
    for (int s = 0; s < 16; s++) {
        int r = 8 * s + wid;
        size_t off = base + (size_t)r * 2048 + lane * 4;
        float4 p = *(const float4*)&prev[off];
        float4 v = *(const float4*)&sC[r * 132 + lane * 4];
        float4 o;
        o.x = v.x + p.x; o.y = v.y + p.y; o.z = v.z + p.z; o.w = v.w + p.w;
        *(float4*)&qk[off] = o;
        float es = __expf(o.x) + __expf(o.y) + __expf(o.z) + __expf(o.w);
#pragma unroll
        for (int d = 16; d > 0; d >>= 1)
            es += __shfl_xor_sync(0xffffffffu, es, d);
        if (lane == 0) atomicAdd(&g_l[h * 2048 + i0 + r], es);
    }
}

// K5: AV via split-bf16 mma; P = exp(qk), divide by g_l; writes g_oh/g_ol.
#define AV_SMEM 104448
__global__ void __launch_bounds__(256, 2)
av_mma_kernel(const float* __restrict__ qk)
{
    extern __shared__ __nv_bfloat16 avs[];
    __nv_bfloat16* sPh = avs;                       // [128][136]
    __nv_bfloat16* sPl = avs + 128 * 136;
    __nv_bfloat16* sVh = avs + 2 * 128 * 136;       // [64][136]
    __nv_bfloat16* sVl = avs + 2 * 128 * 136 + 64 * 136;
    const int i0 = blockIdx.x * 128, h = blockIdx.y;
    const int t = threadIdx.x, wid = t >> 5, lane = t & 31;
    const int wm = wid >> 1, wn = wid & 1;          // warp tile 32(m) x 32(n)

    float acc[2][4][4];
#pragma unroll
    for (int mi = 0; mi < 2; mi++)
#pragma unroll
        for (int o = 0; o < 4; o++)
#pragma unroll
            for (int e = 0; e < 4; e++) acc[mi][o][e] = 0.f;

    for (int jb = 0; jb < 16; jb++) {
        const int j0 = jb * 128;
#pragma unroll
        for (int s = 0; s < 16; s++) {              // P = exp(qk), split
            int e = t + 256 * s;
            int r = e >> 5, c4 = e & 31;
            size_t off = ((size_t)(h * 2048 + i0 + r)) * 2048 + j0 + c4 * 4;
            float4 x = *(const float4*)&qk[off];
            float4 p;
            p.x = __expf(x.x); p.y = __expf(x.y);
            p.z = __expf(x.z); p.w = __expf(x.w);
            split_store(p, &sPh[r * 136 + c4 * 4], &sPl[r * 136 + c4 * 4]);
        }
#pragma unroll
        for (int s = 0; s < 4; s++) {               // V^T tiles hi/lo (uint4)
            int e = t + 256 * s;
            int d = e >> 4, c16 = e & 15;
            *(uint4*)&sVh[d * 136 + c16 * 8] =
                *(const uint4*)&g_vth[h][d][j0 + c16 * 8];
            *(uint4*)&sVl[d * 136 + c16 * 8] =
                *(const uint4*)&g_vtl[h][d][j0 + c16 * 8];
        }
        __syncthreads();
        const uint32_t bPh = smem_u32(sPh), bPl = smem_u32(sPl);
        const uint32_t bVh = smem_u32(sVh), bVl = smem_u32(sVl);
#pragma unroll
        for (int kk = 0; kk < 128; kk += 16) {
            uint32_t ah[2][4], al[2][4], bv[4][2];
#pragma unroll
            for (int mi = 0; mi < 2; mi++) {
                uint32_t off = (uint32_t)((wm * 32 + mi * 16 + (lane & 15)) * 136
                                          + kk + (lane >> 4) * 8) * 2;
                ldm_x4(ah[mi], bPh + off);
                ldm_x4(al[mi], bPl + off);
            }
#pragma unroll
            for (int nb = 0; nb < 2; nb++) {        // Vh frags
                uint32_t off = (uint32_t)((wn * 32 + nb * 16 + (lane & 15)) * 136
                                          + kk + (lane >> 4) * 8) * 2;
                uint32_t r4[4];
                ldm_x4(r4, bVh + off);
                bv[nb * 2 + 0][0] = r4[0]; bv[nb * 2 + 0][1] = r4[2];
                bv[nb * 2 + 1][0] = r4[1]; bv[nb * 2 + 1][1] = r4[3];
            }
#pragma unroll
            for (int mi = 0; mi < 2; mi++)
#pragma unroll
                for (int o = 0; o < 4; o++) {
                    mma_16816(acc[mi][o], ah[mi], bv[o][0], bv[o][1]);
                    mma_16816(acc[mi][o], al[mi], bv[o][0], bv[o][1]);
                }
#pragma unroll
            for (int nb = 0; nb < 2; nb++) {        // Vl frags
                uint32_t off = (uint32_t)((wn * 32 + nb * 16 + (lane & 15)) * 136
                                          + kk + (lane >> 4) * 8) * 2;
                uint32_t r4[4];
                ldm_x4(r4, bVl + off);
                bv[nb * 2 + 0][0] = r4[0]; bv[nb * 2 + 0][1] = r4[2];
                bv[nb * 2 + 1][0] = r4[1]; bv[nb * 2 + 1][1] = r4[3];
            }
#pragma unroll
            for (int mi = 0; mi < 2; mi++)
#pragma unroll
                for (int o = 0; o < 4; o++)
                    mma_16816(acc[mi][o], ah[mi], bv[o][0], bv[o][1]);
        }
        __syncthreads();
    }
#pragma unroll
    for (int mi = 0; mi < 2; mi++)
#pragma unroll
        for (int o = 0; o < 4; o++)
#pragma unroll
            for (int half = 0; half < 2; half++) {
                int row = i0 + wm * 32 + mi * 16 + (lane >> 2) + half * 8;
                float invl = 1.0f / g_l[h * 2048 + row];
                int col = h * 64 + wn * 32 + o * 8 + (lane & 3) * 2;
                float o0 = acc[mi][o][half * 2 + 0] * invl;
                float o1 = acc[mi][o][half * 2 + 1] * invl;
                __nv_bfloat16 h0 = __float2bfloat16(o0);
                __nv_bfloat16 h1 = __float2bfloat16(o1);
                __nv_bfloat16 l0 = __float2bfloat16(o0 - __bfloat162float(h0));
                __nv_bfloat16 l1 = __float2bfloat16(o1 - __bfloat162float(h1));
                __nv_bfloat162 ph; ph.x = h0; ph.y = h1;
                __nv_bfloat162 pl; pl.x = l0; pl.y = l1;
                *(__nv_bfloat162*)&g_oh[row][col] = ph;
                *(__nv_bfloat162*)&g_ol[row][col] = pl;
            }
}

// --------------------------------------------------------------------------
extern "C" void kernel_launch(void* const* d_in, const int* in_sizes, int n_in,
                              void* d_out, int out_size)
{
    const float* x    = (const float*)d_in[0];
    const float* prev = (const float*)d_in[1];
    const float* Wq   = (const float*)d_in[2];
    const float* Wk   = (const float*)d_in[3];
    const float* Wv   = (const float*)d_in[4];
    const float* Wo   = (const float*)d_in[5];
    const float* cq   = (const float*)d_in[6];
    const float* ck   = (const float*)d_in[7];
    const float* cv   = (const float*)d_in[8];
    const float* relw = (const float*)d_in[9];

    float* out = (float*)d_out;                 // (1,2048,1024)
    float* qk  = out + (size_t)NW * NBINS;      // (1,16,2048,2048)

    const size_t QK_SMEM = (size_t)4 * 128 * QK_RS * sizeof(__nv_bfloat16); // 73728
    cudaFuncSetAttribute(proj3_kernel,    cudaFuncAttributeMaxDynamicSharedMemorySize, GP_SMEM);
    cudaFuncSetAttribute(out_pipe_kernel, cudaFuncAttributeMaxDynamicSharedMemorySize, GP_SMEM);
    cudaFuncSetAttribute(qk_mma_kernel,   cudaFuncAttributeMaxDynamicSharedMemorySize, (int)QK_SMEM);
    cudaFuncSetAttribute(av_mma_kernel,   cudaFuncAttributeMaxDynamicSharedMemorySize, AV_SMEM);

    zero_l_kernel<<<(NH * NW) / 256, 256>>>();
    cvt_x_kernel<<<(NW * NBINS) / 1024, 256>>>(x);
    cvt_w_kernel<<<dim3((NBINS * NBINS) / 1024, 4), 256>>>(Wq, Wk, Wv, Wo);

    proj3_kernel<<<dim3(8, 32, 3), 128, GP_SMEM>>>();

    conv_kernel<<<(3 * NW * NBINS) / 256, 256>>>(cq, ck, cv);
    relw_cvt_kernel<<<(HD * NW) / 256, 256>>>(relw);
    vt_split_kernel<<<dim3(32, 16), 256>>>();
    qk_mma_kernel<<<dim3(16, 16, 16), 256, QK_SMEM>>>(prev, qk);
    av_mma_kernel<<<dim3(16, 16), 256, AV_SMEM>>>(qk);
    out_pipe_kernel<<<dim3(8, 32), 128, GP_SMEM>>>(out);
}